// round 8
// baseline (speedup 1.0000x reference)
#include <cuda_runtime.h>
#include <cstdint>

#define D        64
#define D4       16
#define E        6
#define ROWS     128               // rows per tile
#define THREADS  256               // 2 threads per row
#define ROW_B    256               // bytes per row (unpadded; swizzled reads)
#define SLOT_BYTES (ROWS * ROW_B)          // 32768
#define OFF_SW     (2 * SLOT_BYTES)        // 65536
#define OFF_SB     (OFF_SW + E * D * 4)    // 67072
#define OFF_MB0    (OFF_SB + 32)           // 67104
#define OFF_MB1    (OFF_MB0 + 8)           // 67112
#define SMEM_TOTAL (OFF_MB1 + 8 + 48)      // 67168

// ---------------- PTX helpers ----------------
__device__ __forceinline__ uint32_t smem_u32(const void* p) {
    uint32_t a;
    asm("{ .reg .u64 t; cvta.to.shared.u64 t, %1; cvt.u32.u64 %0, t; }" : "=r"(a) : "l"(p));
    return a;
}
#define MBAR_INIT(addr, cnt) \
    asm volatile("mbarrier.init.shared.b64 [%0], %1;" :: "r"(addr), "r"(cnt) : "memory")
#define MBAR_EXPECT_TX(addr, bytes) \
    asm volatile("mbarrier.arrive.expect_tx.shared.b64 _, [%0], %1;" :: "r"(addr), "r"(bytes) : "memory")
#define MBAR_WAIT(addr, parity) do {                                              \
    uint32_t _m = (addr), _p = (parity);                                          \
    asm volatile(                                                                 \
        "{\n\t.reg .pred P1;\n\t"                                                 \
        "WL_%=:\n\t"                                                              \
        "mbarrier.try_wait.parity.acquire.cta.shared::cta.b64 P1, [%0], %1, 0x989680;\n\t" \
        "@P1 bra.uni WD_%=;\n\t"                                                  \
        "bra.uni WL_%=;\n\t"                                                      \
        "WD_%=:\n\t}"                                                             \
        :: "r"(_m), "r"(_p) : "memory");                                          \
} while (0)
#define BULK_CP(dst_smem, src_gmem, bytes, mbar) \
    asm volatile("cp.async.bulk.shared::cta.global.mbarrier::complete_tx::bytes [%0], [%1], %2, [%3];" \
                 :: "r"(dst_smem), "l"(src_gmem), "r"(bytes), "r"(mbar) : "memory")
#define FMA_F32X2(d, a, b, c) \
    asm("fma.rn.f32x2 %0, %1, %2, %3;" : "=l"(d) : "l"(a), "l"(b), "l"(c))
#define UNPACK2(lo, hi, v) \
    asm("mov.b64 {%0, %1}, %2;" : "=f"(lo), "=f"(hi) : "l"(v))

// ---------------- kernel ----------------
__global__ __launch_bounds__(THREADS, 3)
void gate_kernel(const float* __restrict__ h,
                 const float* __restrict__ W,
                 const float* __restrict__ b,
                 float* __restrict__ out,
                 int n, int ntiles)
{
    extern __shared__ char smem[];
    const uint32_t sbase = smem_u32(smem);
    const uint32_t mb[2] = { sbase + OFF_MB0, sbase + OFF_MB1 };
    const int tid  = threadIdx.x;
    const int lane = tid & 31;
    // 2 threads per row: lanes l and l^16 share row (w*16 + (l&15)); half = bit4
    const int rowInTile = (tid >> 5) * 16 + (lane & 15);
    const int half      = (lane >> 4) & 1;
    const int swz       = rowInTile & 7;        // k-permutation for bank-conflict-free reads

    float4* sw4 = reinterpret_cast<float4*>(smem + OFF_SW);
    float*  sb  = reinterpret_cast<float*>(smem + OFF_SB);
    if (tid < E * D4) sw4[tid] = reinterpret_cast<const float4*>(W)[tid];
    if (tid >= 96 && tid < 96 + E) sb[tid - 96] = b[tid - 96];
    if (tid == 0) { MBAR_INIT(mb[0], 1); MBAR_INIT(mb[1], 1); }
    __syncthreads();

    const int stride = gridDim.x;
    const int t0 = blockIdx.x;

    // one bulk copy per tile, issued by thread 0 only
    auto prefetch = [&](int tile, int slot) {
        if (tid == 0) {
            long long rowBase = (long long)tile * ROWS;
            int rows = (n - rowBase >= ROWS) ? ROWS : (int)(n - rowBase);
            uint32_t bytes = rows * ROW_B;
            MBAR_EXPECT_TX(mb[slot], bytes);
            BULK_CP(sbase + slot * SLOT_BYTES, h + rowBase * D, bytes, mb[slot]);
        }
    };

    prefetch(t0, 0);
    if (t0 + stride < ntiles) prefetch(t0 + stride, 1);

    // W for this thread's half, as 16B units: byte = OFF_SW + half*128 + e*256 + ke*16
    const ulonglong2* swh = reinterpret_cast<const ulonglong2*>(smem + OFF_SW + half * 128);

    int ph0 = 0, ph1 = 0;
    for (int t = t0; t < ntiles; ) {
        #pragma unroll
        for (int s = 0; s < 2; ++s) {
            if (t >= ntiles) break;
            if (s == 0) { MBAR_WAIT(mb[0], ph0); ph0 ^= 1; }
            else        { MBAR_WAIT(mb[1], ph1); ph1 ^= 1; }

            long long row = (long long)t * ROWS + rowInTile;
            if (row < n) {
                // this thread's half-row (8 float4), read in swizzled k order
                const ulonglong2* hr = reinterpret_cast<const ulonglong2*>(
                    smem + s * SLOT_BYTES + rowInTile * ROW_B + half * 128);

                uint64_t acc0[E], acc1[E];
                #pragma unroll
                for (int e = 0; e < E; ++e) { acc0[e] = 0ull; acc1[e] = 0ull; }

                #pragma unroll
                for (int k = 0; k < 8; ++k) {
                    int ke = k ^ swz;                       // bank-conflict-free phase tiling
                    ulonglong2 hv = hr[ke];
                    #pragma unroll
                    for (int e = 0; e < E; ++e) {
                        ulonglong2 wv = swh[e * D4 + ke];   // matching W elements
                        FMA_F32X2(acc0[e], hv.x, wv.x, acc0[e]);
                        FMA_F32X2(acc1[e], hv.y, wv.y, acc1[e]);
                    }
                }

                float g[E];
                #pragma unroll
                for (int e = 0; e < E; ++e) {
                    float a0, a1, a2, a3;
                    UNPACK2(a0, a1, acc0[e]);
                    UNPACK2(a2, a3, acc1[e]);
                    float mine  = ((a0 + a2) + (a1 + a3));
                    float other = __shfl_xor_sync(0xffffffffu, mine, 16);
                    float lo = half ? other : mine;
                    float hi = half ? mine  : other;
                    g[e] = (lo + hi) + sb[e];
                }

                // top-2, strict >, earliest index wins (matches jax.lax.top_k)
                int i1 = 0; float m1 = g[0];
                #pragma unroll
                for (int e = 1; e < E; ++e) if (g[e] > m1) { m1 = g[e]; i1 = e; }
                int i2 = -1; float m2 = -3.402823466e+38f;
                #pragma unroll
                for (int e = 0; e < E; ++e) if (e != i1 && g[e] > m2) { m2 = g[e]; i2 = e; }

                float ex = __expf(m2 - m1);
                float p1 = 1.0f / (1.0f + ex);
                float p2 = ex * p1;

                float o[E];
                #pragma unroll
                for (int e = 0; e < E; ++e)
                    o[e] = (e == i1) ? p1 : ((e == i2) ? p2 : 0.0f);

                // split the 24B row store across the lane pair (all STG.64, 8B aligned)
                float2* op = reinterpret_cast<float2*>(out + row * (long long)E);
                if (half == 0) {
                    op[0] = make_float2(o[0], o[1]);
                    op[1] = make_float2(o[2], o[3]);
                } else {
                    op[2] = make_float2(o[4], o[5]);
                }
            }

            __syncthreads();                       // slot s fully consumed
            int tn = t + 2 * stride;               // refill slot s
            if (tn < ntiles) prefetch(tn, s);
            t += stride;
        }
    }
}

extern "C" void kernel_launch(void* const* d_in, const int* in_sizes, int n_in,
                              void* d_out, int out_size)
{
    const float* h = (const float*)d_in[0];
    const float* W = (const float*)d_in[1];
    const float* b = (const float*)d_in[2];
    float* out = (float*)d_out;

    int n = in_sizes[0] / D;
    int ntiles = (n + ROWS - 1) / ROWS;

    cudaFuncSetAttribute(gate_kernel, cudaFuncAttributeMaxDynamicSharedMemorySize, SMEM_TOTAL);

    int grid = 148 * 3;                 // 3 blocks/SM resident (~67 KB smem each)
    if (grid > ntiles) grid = ntiles;
    gate_kernel<<<grid, THREADS, SMEM_TOTAL>>>(h, W, b, out, n, ntiles);
}

// round 9
// speedup vs baseline: 1.3294x; 1.3294x over previous
#include <cuda_runtime.h>
#include <cuda.h>
#include <cstdint>

#define D        64
#define E        6
#define ROWS     128               // rows per tile (= 256 half-rows)
#define HROWS    256
#define THREADS  256               // 1 thread per half-row
#define SLOT_BYTES (HROWS * 128)           // 32768
#define OFF_SW0    (2 * SLOT_BYTES)        // 65536  (bank offset 0)
#define OFF_SW1    (OFF_SW0 + 768 + 64)    // 66368  (mod 128 == 64 -> bank offset 16)
#define OFF_SB     67136
#define OFF_MB0    67168
#define OFF_MB1    67176
#define SMEM_TOTAL 67264

// ---------------- PTX helpers ----------------
__device__ __forceinline__ uint32_t smem_u32(const void* p) {
    uint32_t a;
    asm("{ .reg .u64 t; cvta.to.shared.u64 t, %1; cvt.u32.u64 %0, t; }" : "=r"(a) : "l"(p));
    return a;
}
#define MBAR_INIT(addr, cnt) \
    asm volatile("mbarrier.init.shared.b64 [%0], %1;" :: "r"(addr), "r"(cnt) : "memory")
#define MBAR_EXPECT_TX(addr, bytes) \
    asm volatile("mbarrier.arrive.expect_tx.shared.b64 _, [%0], %1;" :: "r"(addr), "r"(bytes) : "memory")
#define MBAR_WAIT(addr, parity) do {                                              \
    uint32_t _m = (addr), _p = (parity);                                          \
    asm volatile(                                                                 \
        "{\n\t.reg .pred P1;\n\t"                                                 \
        "WL_%=:\n\t"                                                              \
        "mbarrier.try_wait.parity.acquire.cta.shared::cta.b64 P1, [%0], %1, 0x989680;\n\t" \
        "@P1 bra.uni WD_%=;\n\t"                                                  \
        "bra.uni WL_%=;\n\t"                                                      \
        "WD_%=:\n\t}"                                                             \
        :: "r"(_m), "r"(_p) : "memory");                                          \
} while (0)
#define TMA_LOAD2D(dst, map, x, y, mbar) \
    asm volatile("cp.async.bulk.tensor.2d.shared::cta.global.tile.mbarrier::complete_tx::bytes " \
                 "[%0], [%1, {%2, %3}], [%4];" \
                 :: "r"(dst), "l"(map), "r"(x), "r"(y), "r"(mbar) : "memory")
#define FMA_F32X2(d, a, b, c) \
    asm("fma.rn.f32x2 %0, %1, %2, %3;" : "=l"(d) : "l"(a), "l"(b), "l"(c))
#define UNPACK2(lo, hi, v) \
    asm("mov.b64 {%0, %1}, %2;" : "=f"(lo), "=f"(hi) : "l"(v))

// ---------------- kernel ----------------
__global__ __launch_bounds__(THREADS, 3)
void gate_kernel(const __grid_constant__ CUtensorMap tmap,
                 const float* __restrict__ W,
                 const float* __restrict__ b,
                 float* __restrict__ out,
                 int n, int ntiles)
{
    extern __shared__ char smem[];
    const uint32_t sbase = smem_u32(smem);
    const uint32_t mb[2] = { sbase + OFF_MB0, sbase + OFF_MB1 };
    const int tid  = threadIdx.x;
    const int half = tid & 1;                  // which 32-float half of the row
    const int rowInTile = tid >> 1;
    const int swz  = tid & 7;                  // SW128 phase of this half-row

    // W staged as two compact halves at bank-disjoint offsets:
    //   W0[e][k] (floats e*64 + k*4 .. +3)      at OFF_SW0 + e*128 + k*16   (banks 4k..)
    //   W1[e][k] (floats e*64 + 32 + k*4 .. +3) at OFF_SW1 + e*128 + k*16   (banks 16+4k..)
    if (tid < 48) {
        int e = tid >> 3, k = tid & 7;
        *reinterpret_cast<float4*>(smem + OFF_SW0 + e * 128 + k * 16) =
            reinterpret_cast<const float4*>(W)[e * 16 + k];
    } else if (tid >= 64 && tid < 112) {
        int e = (tid - 64) >> 3, k = tid & 7;
        *reinterpret_cast<float4*>(smem + OFF_SW1 + e * 128 + k * 16) =
            reinterpret_cast<const float4*>(W)[e * 16 + 8 + k];
    } else if (tid >= 128 && tid < 128 + E) {
        reinterpret_cast<float*>(smem + OFF_SB)[tid - 128] = b[tid - 128];
    }
    if (tid == 0) { MBAR_INIT(mb[0], 1); MBAR_INIT(mb[1], 1); }
    __syncthreads();

    const int stride = gridDim.x;
    const int t0 = blockIdx.x;
    const CUtensorMap* mp = &tmap;

    // one TMA 2D tile load per slot (SW128 swizzle applied by hardware)
    auto prefetch = [&](int tile, int slot) {
        if (tid == 0) {
            MBAR_EXPECT_TX(mb[slot], SLOT_BYTES);
            TMA_LOAD2D(sbase + slot * SLOT_BYTES, mp, 0, tile * HROWS, mb[slot]);
        }
    };

    prefetch(t0, 0);
    if (t0 + stride < ntiles) prefetch(t0 + stride, 1);

    const char* wbase = smem + (half ? OFF_SW1 : OFF_SW0);
    const float* sb = reinterpret_cast<const float*>(smem + OFF_SB);

    int ph0 = 0, ph1 = 0;
    for (int t = t0; t < ntiles; ) {
        #pragma unroll
        for (int s = 0; s < 2; ++s) {
            if (t >= ntiles) break;
            if (s == 0) { MBAR_WAIT(mb[0], ph0); ph0 ^= 1; }
            else        { MBAR_WAIT(mb[1], ph1); ph1 ^= 1; }

            long long row = (long long)t * ROWS + rowInTile;
            if (row < n) {
                // half-row hr = tid: element k stored at unit k ^ (hr&7) (SW128)
                const char* hb = smem + s * SLOT_BYTES + tid * 128;

                uint64_t acc0[E], acc1[E];
                #pragma unroll
                for (int e = 0; e < E; ++e) { acc0[e] = 0ull; acc1[e] = 0ull; }

                #pragma unroll
                for (int k = 0; k < 8; ++k) {
                    ulonglong2 hv = *reinterpret_cast<const ulonglong2*>(
                        hb + ((k ^ swz) << 4));            // -> original element k
                    #pragma unroll
                    for (int e = 0; e < E; ++e) {
                        ulonglong2 wv = *reinterpret_cast<const ulonglong2*>(
                            wbase + e * 128 + k * 16);     // phase-uniform -> broadcast
                        FMA_F32X2(acc0[e], hv.x, wv.x, acc0[e]);
                        FMA_F32X2(acc1[e], hv.y, wv.y, acc1[e]);
                    }
                }

                float g[E];
                #pragma unroll
                for (int e = 0; e < E; ++e) {
                    float a0, a1, a2, a3;
                    UNPACK2(a0, a1, acc0[e]);
                    UNPACK2(a2, a3, acc1[e]);
                    float mine  = ((a0 + a2) + (a1 + a3));
                    float other = __shfl_xor_sync(0xffffffffu, mine, 1);  // partner half
                    float lo = half ? other : mine;
                    float hi = half ? mine  : other;
                    g[e] = (lo + hi) + sb[e];
                }

                // top-2, strict >, earliest index wins (matches jax.lax.top_k)
                int i1 = 0; float m1 = g[0];
                #pragma unroll
                for (int e = 1; e < E; ++e) if (g[e] > m1) { m1 = g[e]; i1 = e; }
                int i2 = -1; float m2 = -3.402823466e+38f;
                #pragma unroll
                for (int e = 0; e < E; ++e) if (e != i1 && g[e] > m2) { m2 = g[e]; i2 = e; }

                float ex = __expf(m2 - m1);
                float p1 = 1.0f / (1.0f + ex);
                float p2 = ex * p1;

                float o[E];
                #pragma unroll
                for (int e = 0; e < E; ++e)
                    o[e] = (e == i1) ? p1 : ((e == i2) ? p2 : 0.0f);

                // lane pair splits the 24B row store (all STG.64, 8B aligned)
                float2* op = reinterpret_cast<float2*>(out + row * (long long)E);
                if (half == 0) {
                    op[0] = make_float2(o[0], o[1]);
                    op[1] = make_float2(o[2], o[3]);
                } else {
                    op[2] = make_float2(o[4], o[5]);
                }
            }

            __syncthreads();                       // slot s fully consumed
            int tn = t + 2 * stride;               // refill slot s
            if (tn < ntiles) prefetch(tn, s);
            t += stride;
        }
    }
}

// ---------------- host ----------------
typedef CUresult (*PFN_encodeTiled)(
    CUtensorMap*, CUtensorMapDataType, cuuint32_t, void*,
    const cuuint64_t*, const cuuint64_t*, const cuuint32_t*, const cuuint32_t*,
    CUtensorMapInterleave, CUtensorMapSwizzle, CUtensorMapL2promotion,
    CUtensorMapFloatOOBfill);

extern "C" void kernel_launch(void* const* d_in, const int* in_sizes, int n_in,
                              void* d_out, int out_size)
{
    const float* h = (const float*)d_in[0];
    const float* W = (const float*)d_in[1];
    const float* b = (const float*)d_in[2];
    float* out = (float*)d_out;

    int n = in_sizes[0] / D;
    int ntiles = (n + ROWS - 1) / ROWS;

    // Encode TMA descriptor: h viewed as 2D [32 floats x 2N half-rows], SW128.
    static PFN_encodeTiled encode = nullptr;
    if (!encode) {
        cudaDriverEntryPointQueryResult qr;
        void* fp = nullptr;
        cudaGetDriverEntryPointByVersion("cuTensorMapEncodeTiled", &fp, 12000,
                                         cudaEnableDefault, &qr);
        encode = (PFN_encodeTiled)fp;
    }

    CUtensorMap tmap;
    cuuint64_t dims[2]    = { 32, (cuuint64_t)n * 2 };
    cuuint64_t strides[1] = { 128 };
    cuuint32_t box[2]     = { 32, HROWS };
    cuuint32_t estr[2]    = { 1, 1 };
    encode(&tmap, CU_TENSOR_MAP_DATA_TYPE_FLOAT32, 2, (void*)h,
           dims, strides, box, estr,
           CU_TENSOR_MAP_INTERLEAVE_NONE, CU_TENSOR_MAP_SWIZZLE_128B,
           CU_TENSOR_MAP_L2_PROMOTION_L2_128B, CU_TENSOR_MAP_FLOAT_OOB_FILL_NONE);

    cudaFuncSetAttribute(gate_kernel, cudaFuncAttributeMaxDynamicSharedMemorySize, SMEM_TOTAL);

    int grid = 148 * 3;                 // 3 blocks/SM resident (~67 KB smem each)
    if (grid > ntiles) grid = ntiles;
    gate_kernel<<<grid, THREADS, SMEM_TOTAL>>>(tmap, W, b, out, n, ntiles);
}